// round 1
// baseline (speedup 1.0000x reference)
#include <cuda_runtime.h>
#include <math.h>

#define TT 128
#define BB 256
#define DD 512
#define HH 1024
#define GG 4096   // 4*H

// ---------------- scratch (static device globals; no runtime alloc) ----------
__device__ __align__(16) float g_x[(size_t)TT * BB * HH];     // relu(inputs@W1^T+b1)  128 MB
__device__ __align__(16) float g_xg[(size_t)TT * BB * GG];    // x@W_ih^T + bias       512 MB
__device__ __align__(16) float g_h[BB * HH];
__device__ __align__(16) float g_c[BB * HH];
__device__ __align__(16) float g_gates[BB * GG];
__device__ __align__(16) float g_bias[GG];

// ---------------- tiled fp32 NT GEMM: C[m][n] = sum_k A[m][k]*B[n][k] (+epilogue)
// BM=64, BN=128, BK=16, 256 threads, per-thread 4x8 (two float4 column groups)
template<int RELU, int HAS_BIAS, int HAS_ADD>
__global__ __launch_bounds__(256)
void gemm_nt(const float* __restrict__ A, const float* __restrict__ B,
             const float* __restrict__ bias, const float* __restrict__ Cadd,
             float* __restrict__ C, int M, int N, int K)
{
    __shared__ __align__(16) float As[16][64];
    __shared__ __align__(16) float Bs[16][128];

    const int tid   = threadIdx.x;
    const int mBase = blockIdx.y * 64;
    const int nBase = blockIdx.x * 128;

    const int arow = tid >> 2;          // 0..63
    const int acol = (tid & 3) * 4;     // 0,4,8,12
    const int tx   = tid & 15;          // 0..15
    const int ty   = tid >> 4;          // 0..15

    float acc[4][8];
#pragma unroll
    for (int i = 0; i < 4; i++)
#pragma unroll
        for (int j = 0; j < 8; j++) acc[i][j] = 0.0f;

    const float* Ag  = A + (size_t)(mBase + arow) * K + acol;
    const float* Bg0 = B + (size_t)(nBase + arow) * K + acol;
    const float* Bg1 = Bg0 + (size_t)64 * K;

    for (int kt = 0; kt < K; kt += 16) {
        float4 av  = *(const float4*)(Ag  + kt);
        float4 bv0 = *(const float4*)(Bg0 + kt);
        float4 bv1 = *(const float4*)(Bg1 + kt);

        As[acol + 0][arow] = av.x;  As[acol + 1][arow] = av.y;
        As[acol + 2][arow] = av.z;  As[acol + 3][arow] = av.w;
        Bs[acol + 0][arow] = bv0.x; Bs[acol + 1][arow] = bv0.y;
        Bs[acol + 2][arow] = bv0.z; Bs[acol + 3][arow] = bv0.w;
        Bs[acol + 0][arow + 64] = bv1.x; Bs[acol + 1][arow + 64] = bv1.y;
        Bs[acol + 2][arow + 64] = bv1.z; Bs[acol + 3][arow + 64] = bv1.w;
        __syncthreads();

#pragma unroll
        for (int kk = 0; kk < 16; kk++) {
            float4 a  = *(const float4*)&As[kk][ty * 4];
            float4 b0 = *(const float4*)&Bs[kk][tx * 4];
            float4 b1 = *(const float4*)&Bs[kk][tx * 4 + 64];
            float ar[4] = {a.x, a.y, a.z, a.w};
            float br[8] = {b0.x, b0.y, b0.z, b0.w, b1.x, b1.y, b1.z, b1.w};
#pragma unroll
            for (int i = 0; i < 4; i++)
#pragma unroll
                for (int j = 0; j < 8; j++)
                    acc[i][j] = fmaf(ar[i], br[j], acc[i][j]);
        }
        __syncthreads();
    }

#pragma unroll
    for (int i = 0; i < 4; i++) {
        const int m = mBase + ty * 4 + i;
#pragma unroll
        for (int g2 = 0; g2 < 2; g2++) {
            const int n = nBase + tx * 4 + g2 * 64;
            float4 r = make_float4(acc[i][g2 * 4 + 0], acc[i][g2 * 4 + 1],
                                   acc[i][g2 * 4 + 2], acc[i][g2 * 4 + 3]);
            if (HAS_BIAS) {
                float4 bb = *(const float4*)(bias + n);
                r.x += bb.x; r.y += bb.y; r.z += bb.z; r.w += bb.w;
            }
            if (HAS_ADD) {
                float4 cc = *(const float4*)(Cadd + (size_t)m * N + n);
                r.x += cc.x; r.y += cc.y; r.z += cc.z; r.w += cc.w;
            }
            if (RELU) {
                r.x = fmaxf(r.x, 0.0f); r.y = fmaxf(r.y, 0.0f);
                r.z = fmaxf(r.z, 0.0f); r.w = fmaxf(r.w, 0.0f);
            }
            *(float4*)(C + (size_t)m * N + n) = r;
        }
    }
}

// ---------------- small helpers ----------------
__global__ void combine_bias_k(const float* __restrict__ b_ih, const float* __restrict__ b_hh)
{
    int i = blockIdx.x * blockDim.x + threadIdx.x;
    if (i < GG) g_bias[i] = b_ih[i] + b_hh[i];
}

__global__ void init_state_k(const float* __restrict__ h0, const float* __restrict__ c0)
{
    int i = blockIdx.x * blockDim.x + threadIdx.x;
    if (i < BB * HH) { g_h[i] = h0[i]; g_c[i] = c0[i]; }
}

__device__ __forceinline__ float sigf(float x) { return 1.0f / (1.0f + __expf(-x)); }

// one block per batch element, 1024 threads (one per hidden unit)
__global__ __launch_bounds__(1024)
void lstm_cell_k(const float* __restrict__ W_out, const float* __restrict__ b_out,
                 float* __restrict__ out, float* __restrict__ hT, float* __restrict__ cT,
                 int t)
{
    const int b = blockIdx.x;
    const int j = threadIdx.x;
    const int gidx = b * GG + j;
    const int hidx = b * HH + j;

    float ig = sigf(g_gates[gidx]);
    float fg = sigf(g_gates[gidx + HH]);
    float gg = tanhf(g_gates[gidx + 2 * HH]);
    float og = sigf(g_gates[gidx + 3 * HH]);

    float c = fg * g_c[hidx] + ig * gg;
    float h = og * tanhf(c);
    g_c[hidx] = c;
    g_h[hidx] = h;

    __shared__ float red[1024];
    red[j] = h * W_out[j];
    __syncthreads();
#pragma unroll
    for (int s = 512; s > 0; s >>= 1) {
        if (j < s) red[j] += red[j + s];
        __syncthreads();
    }
    if (j == 0) out[t * BB + b] = red[0] + b_out[0];

    if (t == TT - 1) { hT[hidx] = h; cT[hidx] = c; }
}

// ---------------- launch ----------------
extern "C" void kernel_launch(void* const* d_in, const int* in_sizes, int n_in,
                              void* d_out, int out_size)
{
    const float* inputs = (const float*)d_in[0];
    const float* h0     = (const float*)d_in[1];
    const float* c0     = (const float*)d_in[2];
    const float* W1     = (const float*)d_in[3];
    const float* b1     = (const float*)d_in[4];
    const float* W_ih   = (const float*)d_in[5];
    const float* W_hh   = (const float*)d_in[6];
    const float* b_ih   = (const float*)d_in[7];
    const float* b_hh   = (const float*)d_in[8];
    const float* W_out  = (const float*)d_in[9];
    const float* b_out  = (const float*)d_in[10];

    float* out = (float*)d_out;               // (T,B,O=1): 32768
    float* hT  = out + TT * BB;               // (1,B,H):   262144
    float* cT  = hT + BB * HH;                // (1,B,H):   262144

    float *px, *pxg, *ph, *pg, *pbias;
    cudaGetSymbolAddress((void**)&px,    g_x);
    cudaGetSymbolAddress((void**)&pxg,   g_xg);
    cudaGetSymbolAddress((void**)&ph,    g_h);
    cudaGetSymbolAddress((void**)&pg,    g_gates);
    cudaGetSymbolAddress((void**)&pbias, g_bias);

    combine_bias_k<<<GG / 256, 256>>>(b_ih, b_hh);
    init_state_k<<<(BB * HH) / 256, 256>>>(h0, c0);

    // x = relu(inputs @ W1^T + b1):  M=T*B=32768, N=H=1024, K=D=512
    {
        dim3 grid(HH / 128, (TT * BB) / 64);
        gemm_nt<1, 1, 0><<<grid, 256>>>(inputs, W1, b1, nullptr, px, TT * BB, HH, DD);
    }
    // xg = x @ W_ih^T + (b_ih + b_hh):  M=32768, N=4H=4096, K=H=1024
    {
        dim3 grid(GG / 128, (TT * BB) / 64);
        gemm_nt<0, 1, 0><<<grid, 256>>>(px, W_ih, pbias, nullptr, pxg, TT * BB, GG, HH);
    }
    // recurrence
    {
        dim3 grid(GG / 128, BB / 64);
        for (int t = 0; t < TT; t++) {
            gemm_nt<0, 0, 1><<<grid, 256>>>(ph, W_hh, nullptr,
                                            pxg + (size_t)t * BB * GG, pg, BB, GG, HH);
            lstm_cell_k<<<BB, HH>>>(W_out, b_out, out, hT, cT, t);
        }
    }
}

// round 3
// speedup vs baseline: 2.2903x; 2.2903x over previous
#include <cuda_runtime.h>
#include <cuda_bf16.h>
#include <math.h>
#include <stdint.h>

#define TT 128
#define BB 256
#define DD 512
#define HH 1024
#define GG 4096   // 4*H

// ===================== scratch (static device globals) ======================
// chunk-major bf16 operand buffers: [2*C chunks][R rows][64 bf16]
// first C chunks = hi, next C chunks = lo. Each row is 128B, tiles contiguous.
__device__ __align__(16) __nv_bfloat16 g_inc [(size_t)16 * 32768 * 64]; // inputs (K=512, C=8)
__device__ __align__(16) __nv_bfloat16 g_xc  [(size_t)32 * 32768 * 64]; // x      (K=1024, C=16)
__device__ __align__(16) __nv_bfloat16 g_w1c [(size_t)16 * 1024  * 64]; // W1
__device__ __align__(16) __nv_bfloat16 g_wihc[(size_t)32 * 4096  * 64]; // W_ih
__device__ __align__(16) __nv_bfloat16 g_whhc[(size_t)32 * 4096  * 64]; // W_hh
__device__ __align__(16) __nv_bfloat16 g_hc  [(size_t)32 * 256   * 64]; // h state (split)
__device__ __align__(16) float g_xg[(size_t)TT * BB * GG];              // 512 MB
__device__ __align__(16) float g_gates[BB * GG];
__device__ __align__(16) float g_c[BB * HH];
__device__ __align__(16) float g_bias[GG];

// ===================== PTX helpers (all legal on plain sm_103) ==============
__device__ __forceinline__ uint32_t smem_u32(const void* p) {
    return (uint32_t)__cvta_generic_to_shared(p);
}
__device__ __forceinline__ void cp_async16(uint32_t dst, const void* src) {
    asm volatile("cp.async.cg.shared.global [%0], [%1], 16;" :: "r"(dst), "l"(src));
}
__device__ __forceinline__ void cp_commit() {
    asm volatile("cp.async.commit_group;" ::: "memory");
}
template<int N>
__device__ __forceinline__ void cp_wait() {
    asm volatile("cp.async.wait_group %0;" :: "n"(N) : "memory");
}
__device__ __forceinline__ void ldsm_x4(uint32_t& r0, uint32_t& r1, uint32_t& r2, uint32_t& r3,
                                        uint32_t addr) {
    asm volatile("ldmatrix.sync.aligned.m8n8.x4.shared.b16 {%0,%1,%2,%3}, [%4];"
                 : "=r"(r0), "=r"(r1), "=r"(r2), "=r"(r3) : "r"(addr));
}
__device__ __forceinline__ void mma16816(float* c, const uint32_t* a, const uint32_t* b) {
    asm volatile(
        "mma.sync.aligned.m16n8k16.row.col.f32.bf16.bf16.f32 "
        "{%0,%1,%2,%3}, {%4,%5,%6,%7}, {%8,%9}, {%0,%1,%2,%3};"
        : "+f"(c[0]), "+f"(c[1]), "+f"(c[2]), "+f"(c[3])
        : "r"(a[0]), "r"(a[1]), "r"(a[2]), "r"(a[3]), "r"(b[0]), "r"(b[1]));
}

__device__ __forceinline__ void store_split(__nv_bfloat16* dst, int M, int Cout,
                                            int m, int n, float v) {
    const __nv_bfloat16 hi = __float2bfloat16(v);
    const __nv_bfloat16 lo = __float2bfloat16(v - __bfloat162float(hi));
    const int chunk = n >> 6, col = n & 63;
    dst[((size_t)chunk * M + m) * 64 + col] = hi;
    dst[((size_t)(Cout + chunk) * M + m) * 64 + col] = lo;
}

// ===================== bf16 split-GEMM via mma.sync ==========================
// C[M,N] = A[M,K] * B[N,K]^T as hi*hi + hi*lo + lo*hi (3 folded passes)
// A,B chunk-major [2C][rows][64]. BM=BN=128, BK=64, 256 threads, double-buffered.
// MODE 0: v=relu(v+aux[n]) -> split store to outSplit
// MODE 1: v=v+aux[n]       -> outF
// MODE 2: v=v+aux[m*N+n]   -> outF
template<int MODE>
__global__ __launch_bounds__(256)
void gemm_mma(const __nv_bfloat16* __restrict__ A, const __nv_bfloat16* __restrict__ B,
              const float* __restrict__ aux, float* __restrict__ outF,
              __nv_bfloat16* __restrict__ outSplit, int M, int N, int C)
{
    extern __shared__ char smraw[];
    const uint32_t sbase = smem_u32(smraw);   // [2 bufs][A 16KB | B 16KB]

    const int tid  = threadIdx.x;
    const int lane = tid & 31;
    const int wid  = tid >> 5;
    const int wm   = wid & 3;       // 4 warps along M (32 rows each)
    const int wn   = wid >> 2;      // 2 warps along N (64 cols each)
    const int mBase = blockIdx.y * 128;
    const int nBase = blockIdx.x * 128;
    const int NIT = 3 * C;

    float c[2][8][4];
#pragma unroll
    for (int i = 0; i < 2; i++)
#pragma unroll
        for (int j = 0; j < 8; j++)
#pragma unroll
            for (int k = 0; k < 4; k++) c[i][j][k] = 0.0f;

    // lane-constant fragment address pieces
    const int lrow_a = ((lane >> 3) & 1) * 8 + (lane & 7);
    const int lrow_b = (lane >> 4) * 8 + (lane & 7);
    const int lxor   = lane & 7;
    const int ahalf  = lane >> 4;
    const int bhalf  = (lane >> 3) & 1;

#define LOAD_CHUNK(i_, buf_)                                                     \
    do {                                                                          \
        const int p_ = (i_) / C, ci_ = (i_) - p_ * C;                             \
        const int ac_ = (p_ == 2) ? (C + ci_) : ci_;                              \
        const int bc_ = (p_ == 1) ? (C + ci_) : ci_;                              \
        const char* As_ = (const char*)(A + ((size_t)ac_ * M + mBase) * 64);      \
        const char* Bs_ = (const char*)(B + ((size_t)bc_ * N + nBase) * 64);      \
        const uint32_t dA_ = sbase + (buf_) * 32768u;                             \
        const uint32_t dB_ = dA_ + 16384u;                                        \
        _Pragma("unroll")                                                         \
        for (int q_ = 0; q_ < 4; q_++) {                                          \
            const int e_ = tid + q_ * 256;                                        \
            const int r_ = e_ >> 3, s_ = e_ & 7;                                  \
            const uint32_t off_ = r_ * 128 + (((uint32_t)(s_ ^ (r_ & 7))) << 4);  \
            cp_async16(dA_ + off_, As_ + r_ * 128 + s_ * 16);                     \
            cp_async16(dB_ + off_, Bs_ + r_ * 128 + s_ * 16);                     \
        }                                                                         \
    } while (0)

    LOAD_CHUNK(0, 0);
    cp_commit();

    for (int i = 0; i < NIT; i++) {
        const int buf = i & 1;
        if (i + 1 < NIT) {
            LOAD_CHUNK(i + 1, (i + 1) & 1);
            cp_commit();
            cp_wait<1>();
        } else {
            cp_wait<0>();
        }
        __syncthreads();

        const uint32_t aTile = sbase + buf * 32768u;
        const uint32_t bTile = aTile + 16384u;
#pragma unroll
        for (int kk = 0; kk < 4; kk++) {
            uint32_t a[2][4], b[8][2];
#pragma unroll
            for (int mt = 0; mt < 2; mt++) {
                const int row = wm * 32 + mt * 16 + lrow_a;
                const uint32_t addr = aTile + row * 128 +
                    (((uint32_t)((kk * 2 + ahalf) ^ lxor)) << 4);
                ldsm_x4(a[mt][0], a[mt][1], a[mt][2], a[mt][3], addr);
            }
#pragma unroll
            for (int bt = 0; bt < 4; bt++) {
                const int row = wn * 64 + bt * 16 + lrow_b;
                const uint32_t addr = bTile + row * 128 +
                    (((uint32_t)((kk * 2 + bhalf) ^ lxor)) << 4);
                uint32_t r0, r1, r2, r3;
                ldsm_x4(r0, r1, r2, r3, addr);
                b[2 * bt][0] = r0;     b[2 * bt][1] = r1;
                b[2 * bt + 1][0] = r2; b[2 * bt + 1][1] = r3;
            }
#pragma unroll
            for (int mt = 0; mt < 2; mt++)
#pragma unroll
                for (int nt = 0; nt < 8; nt++)
                    mma16816(c[mt][nt], a[mt], b[nt]);
        }
        __syncthreads();
    }
#undef LOAD_CHUNK

    // epilogue
    const int g  = lane >> 2;
    const int tg = lane & 3;
    const int Cout = N >> 6;
#pragma unroll
    for (int mt = 0; mt < 2; mt++) {
        const int m0 = mBase + wm * 32 + mt * 16 + g;
#pragma unroll
        for (int nt = 0; nt < 8; nt++) {
            const int n0 = nBase + wn * 64 + nt * 8 + tg * 2;
#pragma unroll
            for (int half = 0; half < 2; half++) {
                const int m = m0 + half * 8;
                const float v0 = c[mt][nt][half * 2 + 0];
                const float v1 = c[mt][nt][half * 2 + 1];
                if (MODE == 0) {
                    store_split(outSplit, M, Cout, m, n0,
                                fmaxf(v0 + aux[n0], 0.0f));
                    store_split(outSplit, M, Cout, m, n0 + 1,
                                fmaxf(v1 + aux[n0 + 1], 0.0f));
                } else if (MODE == 1) {
                    float2 r = make_float2(v0 + aux[n0], v1 + aux[n0 + 1]);
                    *(float2*)(outF + (size_t)m * N + n0) = r;
                } else {
                    const float* ax = aux + (size_t)m * N + n0;
                    float2 r = make_float2(v0 + ax[0], v1 + ax[1]);
                    *(float2*)(outF + (size_t)m * N + n0) = r;
                }
            }
        }
    }
}

// ===================== conversion / pointwise kernels ========================
__global__ void split_k(const float* __restrict__ src, __nv_bfloat16* __restrict__ dst,
                        int R, int K)
{
    const size_t i = (size_t)blockIdx.x * blockDim.x + threadIdx.x;
    const int r = (int)(i / K);
    const int k = (int)(i - (size_t)r * K);
    const float x = src[i];
    const __nv_bfloat16 hi = __float2bfloat16(x);
    const __nv_bfloat16 lo = __float2bfloat16(x - __bfloat162float(hi));
    const int C = K >> 6;
    const int chunk = k >> 6, col = k & 63;
    dst[((size_t)chunk * R + r) * 64 + col] = hi;
    dst[((size_t)(C + chunk) * R + r) * 64 + col] = lo;
}

__global__ void combine_bias_k(const float* __restrict__ b_ih, const float* __restrict__ b_hh)
{
    int i = blockIdx.x * blockDim.x + threadIdx.x;
    if (i < GG) g_bias[i] = b_ih[i] + b_hh[i];
}

__global__ void init_state_k(const float* __restrict__ h0, const float* __restrict__ c0)
{
    const int i = blockIdx.x * blockDim.x + threadIdx.x;   // [0, B*H)
    const int b = i >> 10, j = i & 1023;
    g_c[i] = c0[i];
    const float h = h0[i];
    const __nv_bfloat16 hi = __float2bfloat16(h);
    const __nv_bfloat16 lo = __float2bfloat16(h - __bfloat162float(hi));
    const int chunk = j >> 6, col = j & 63;
    g_hc[((size_t)chunk * BB + b) * 64 + col] = hi;
    g_hc[((size_t)(16 + chunk) * BB + b) * 64 + col] = lo;
}

__device__ __forceinline__ float sigf(float x) { return 1.0f / (1.0f + __expf(-x)); }

__global__ __launch_bounds__(1024)
void lstm_cell_k(const float* __restrict__ W_out, const float* __restrict__ b_out,
                 float* __restrict__ out, float* __restrict__ hT, float* __restrict__ cT,
                 int t)
{
    const int b = blockIdx.x;
    const int j = threadIdx.x;
    const int gidx = b * GG + j;
    const int hidx = b * HH + j;

    const float ig = sigf(g_gates[gidx]);
    const float fg = sigf(g_gates[gidx + HH]);
    const float gg = tanhf(g_gates[gidx + 2 * HH]);
    const float og = sigf(g_gates[gidx + 3 * HH]);

    const float c = fg * g_c[hidx] + ig * gg;
    const float h = og * tanhf(c);
    g_c[hidx] = c;

    const __nv_bfloat16 hi = __float2bfloat16(h);
    const __nv_bfloat16 lo = __float2bfloat16(h - __bfloat162float(hi));
    const int chunk = j >> 6, col = j & 63;
    g_hc[((size_t)chunk * BB + b) * 64 + col] = hi;
    g_hc[((size_t)(16 + chunk) * BB + b) * 64 + col] = lo;

    float v = h * W_out[j];
#pragma unroll
    for (int o = 16; o > 0; o >>= 1) v += __shfl_xor_sync(0xFFFFFFFFu, v, o);
    __shared__ float red[32];
    if ((j & 31) == 0) red[j >> 5] = v;
    __syncthreads();
    if (j < 32) {
        float w = red[j];
#pragma unroll
        for (int o = 16; o > 0; o >>= 1) w += __shfl_xor_sync(0xFFFFFFFFu, w, o);
        if (j == 0) out[t * BB + b] = w + b_out[0];
    }
    if (t == TT - 1) { hT[hidx] = h; cT[hidx] = c; }
}

// ===================== launch ================================================
#define SMEM_BYTES 65536

extern "C" void kernel_launch(void* const* d_in, const int* in_sizes, int n_in,
                              void* d_out, int out_size)
{
    const float* inputs = (const float*)d_in[0];
    const float* h0     = (const float*)d_in[1];
    const float* c0     = (const float*)d_in[2];
    const float* W1     = (const float*)d_in[3];
    const float* b1     = (const float*)d_in[4];
    const float* W_ih   = (const float*)d_in[5];
    const float* W_hh   = (const float*)d_in[6];
    const float* b_ih   = (const float*)d_in[7];
    const float* b_hh   = (const float*)d_in[8];
    const float* W_out  = (const float*)d_in[9];
    const float* b_out  = (const float*)d_in[10];

    float* out = (float*)d_out;               // (T,B,1)
    float* hT  = out + TT * BB;
    float* cT  = hT + BB * HH;

    __nv_bfloat16 *pinc, *pxc, *pw1c, *pwihc, *pwhhc, *phc;
    float *pxg, *pgates, *pbias;
    cudaGetSymbolAddress((void**)&pinc,  g_inc);
    cudaGetSymbolAddress((void**)&pxc,   g_xc);
    cudaGetSymbolAddress((void**)&pw1c,  g_w1c);
    cudaGetSymbolAddress((void**)&pwihc, g_wihc);
    cudaGetSymbolAddress((void**)&pwhhc, g_whhc);
    cudaGetSymbolAddress((void**)&phc,   g_hc);
    cudaGetSymbolAddress((void**)&pxg,   g_xg);
    cudaGetSymbolAddress((void**)&pgates,g_gates);
    cudaGetSymbolAddress((void**)&pbias, g_bias);

    cudaFuncSetAttribute(gemm_mma<0>, cudaFuncAttributeMaxDynamicSharedMemorySize, SMEM_BYTES);
    cudaFuncSetAttribute(gemm_mma<1>, cudaFuncAttributeMaxDynamicSharedMemorySize, SMEM_BYTES);
    cudaFuncSetAttribute(gemm_mma<2>, cudaFuncAttributeMaxDynamicSharedMemorySize, SMEM_BYTES);

    // conversions
    split_k<<<(32768 * 512) / 256, 256>>>(inputs, pinc, 32768, 512);
    split_k<<<(1024 * 512) / 256, 256>>>(W1,   pw1c,  1024, 512);
    split_k<<<(4096 * 1024) / 256, 256>>>(W_ih, pwihc, 4096, 1024);
    split_k<<<(4096 * 1024) / 256, 256>>>(W_hh, pwhhc, 4096, 1024);
    combine_bias_k<<<GG / 256, 256>>>(b_ih, b_hh);
    init_state_k<<<(BB * HH) / 256, 256>>>(h0, c0);

    // GEMM1: x = relu(inputs @ W1^T + b1) -> split store g_xc
    {
        dim3 grid(HH / 128, 32768 / 128);
        gemm_mma<0><<<grid, 256, SMEM_BYTES>>>(pinc, pw1c, b1, nullptr, pxc, 32768, HH, 8);
    }
    // GEMM2: xg = x @ W_ih^T + bias -> g_xg
    {
        dim3 grid(GG / 128, 32768 / 128);
        gemm_mma<1><<<grid, 256, SMEM_BYTES>>>(pxc, pwihc, pbias, pxg, nullptr, 32768, GG, 16);
    }
    // recurrence
    {
        dim3 grid(GG / 128, BB / 128);
        for (int t = 0; t < TT; t++) {
            gemm_mma<2><<<grid, 256, SMEM_BYTES>>>(phc, pwhhc, pxg + (size_t)t * BB * GG,
                                                   pgates, nullptr, BB, GG, 16);
            lstm_cell_k<<<BB, HH>>>(W_out, b_out, out, hT, cT, t);
        }
    }
}

// round 4
// speedup vs baseline: 3.0914x; 1.3498x over previous
#include <cuda_runtime.h>
#include <cuda_bf16.h>
#include <math.h>
#include <stdint.h>

#define TT 128
#define BB 256
#define DD 512
#define HH 1024
#define GG 4096   // 4*H

// ===================== scratch (static device globals) ======================
// chunk-major bf16 operand buffers: [2*C chunks][R rows][64 bf16]
__device__ __align__(16) __nv_bfloat16 g_inc [(size_t)16 * 32768 * 64]; // inputs (K=512, C=8)
__device__ __align__(16) __nv_bfloat16 g_xc  [(size_t)32 * 32768 * 64]; // x      (K=1024, C=16)
__device__ __align__(16) __nv_bfloat16 g_w1c [(size_t)16 * 1024  * 64]; // W1
__device__ __align__(16) __nv_bfloat16 g_wihc[(size_t)32 * 4096  * 64]; // W_ih (gate-perm rows)
__device__ __align__(16) __nv_bfloat16 g_whhc[(size_t)32 * 4096  * 64]; // W_hh (gate-perm rows)
#define HSPLIT ((size_t)32 * 256 * 64)
__device__ __align__(16) __nv_bfloat16 g_hc  [2 * HSPLIT];              // h state, ping-pong
__device__ __align__(16) float g_xg[(size_t)TT * BB * GG];              // gate-perm cols, 512 MB
__device__ __align__(16) float g_c[BB * HH];
__device__ __align__(16) float g_bias[GG];                              // gate-perm

// ===================== PTX helpers ==========================================
__device__ __forceinline__ uint32_t smem_u32(const void* p) {
    return (uint32_t)__cvta_generic_to_shared(p);
}
__device__ __forceinline__ void cp_async16(uint32_t dst, const void* src) {
    asm volatile("cp.async.cg.shared.global [%0], [%1], 16;" :: "r"(dst), "l"(src));
}
__device__ __forceinline__ void cp_commit() {
    asm volatile("cp.async.commit_group;" ::: "memory");
}
template<int N>
__device__ __forceinline__ void cp_wait() {
    asm volatile("cp.async.wait_group %0;" :: "n"(N) : "memory");
}
__device__ __forceinline__ void ldsm_x4(uint32_t& r0, uint32_t& r1, uint32_t& r2, uint32_t& r3,
                                        uint32_t addr) {
    asm volatile("ldmatrix.sync.aligned.m8n8.x4.shared.b16 {%0,%1,%2,%3}, [%4];"
                 : "=r"(r0), "=r"(r1), "=r"(r2), "=r"(r3) : "r"(addr));
}
__device__ __forceinline__ void mma16816(float* c, const uint32_t* a, const uint32_t* b) {
    asm volatile(
        "mma.sync.aligned.m16n8k16.row.col.f32.bf16.bf16.f32 "
        "{%0,%1,%2,%3}, {%4,%5,%6,%7}, {%8,%9}, {%0,%1,%2,%3};"
        : "+f"(c[0]), "+f"(c[1]), "+f"(c[2]), "+f"(c[3])
        : "r"(a[0]), "r"(a[1]), "r"(a[2]), "r"(a[3]), "r"(b[0]), "r"(b[1]));
}

__device__ __forceinline__ void store_split(__nv_bfloat16* dst, int M, int Cout,
                                            int m, int n, float v) {
    const __nv_bfloat16 hi = __float2bfloat16(v);
    const __nv_bfloat16 lo = __float2bfloat16(v - __bfloat162float(hi));
    const int chunk = n >> 6, col = n & 63;
    dst[((size_t)chunk * M + m) * 64 + col] = hi;
    dst[((size_t)(Cout + chunk) * M + m) * 64 + col] = lo;
}

// shared chunk loader: A tile RA rows, B tile RB rows, 128B rows, XOR-swizzled
#define LOAD_CHUNK(A_, B_, M_, N_, C_, mB_, nB_, RA_, RB_, i_, dA_)               \
    do {                                                                          \
        const int p_ = (i_) / (C_), ci_ = (i_) - p_ * (C_);                       \
        const int ac_ = (p_ == 2) ? ((C_) + ci_) : ci_;                           \
        const int bc_ = (p_ == 1) ? ((C_) + ci_) : ci_;                           \
        const char* As_ = (const char*)((A_) + ((size_t)ac_ * (M_) + (mB_)) * 64);\
        const char* Bs_ = (const char*)((B_) + ((size_t)bc_ * (N_) + (nB_)) * 64);\
        const uint32_t dB_ = (dA_) + (RA_) * 128u;                                \
        _Pragma("unroll")                                                         \
        for (int q_ = 0; q_ < (RA_) / 32; q_++) {                                 \
            const int e_ = tid + q_ * 256;                                        \
            const int r_ = e_ >> 3, s_ = e_ & 7;                                  \
            const uint32_t off_ = r_ * 128 + (((uint32_t)(s_ ^ (r_ & 7))) << 4);  \
            cp_async16((dA_) + off_, As_ + r_ * 128 + s_ * 16);                   \
        }                                                                         \
        _Pragma("unroll")                                                         \
        for (int q_ = 0; q_ < (RB_) / 32; q_++) {                                 \
            const int e_ = tid + q_ * 256;                                        \
            const int r_ = e_ >> 3, s_ = e_ & 7;                                  \
            const uint32_t off_ = r_ * 128 + (((uint32_t)(s_ ^ (r_ & 7))) << 4);  \
            cp_async16(dB_ + off_, Bs_ + r_ * 128 + s_ * 16);                     \
        }                                                                         \
    } while (0)

// ===================== big GEMMs (BM=BN=128, 2 CTA/SM) =======================
// MODE 0: v=relu(v+aux[n]) -> split store; MODE 1: v=v+aux[n] -> outF
template<int MODE>
__global__ __launch_bounds__(256, 2)
void gemm_mma(const __nv_bfloat16* __restrict__ A, const __nv_bfloat16* __restrict__ B,
              const float* __restrict__ aux, float* __restrict__ outF,
              __nv_bfloat16* __restrict__ outSplit, int M, int N, int C)
{
    extern __shared__ char smraw[];
    const uint32_t sbase = smem_u32(smraw);   // [2 bufs][A 16KB | B 16KB]

    const int tid  = threadIdx.x;
    const int lane = tid & 31;
    const int wid  = tid >> 5;
    const int wm   = wid & 3;
    const int wn   = wid >> 2;
    const int mBase = blockIdx.y * 128;
    const int nBase = blockIdx.x * 128;
    const int NIT = 3 * C;

    float c[2][8][4];
#pragma unroll
    for (int i = 0; i < 2; i++)
#pragma unroll
        for (int j = 0; j < 8; j++)
#pragma unroll
            for (int k = 0; k < 4; k++) c[i][j][k] = 0.0f;

    const int lrow_a = ((lane >> 3) & 1) * 8 + (lane & 7);
    const int lrow_b = (lane >> 4) * 8 + (lane & 7);
    const int lxor   = lane & 7;
    const int ahalf  = lane >> 4;
    const int bhalf  = (lane >> 3) & 1;

    LOAD_CHUNK(A, B, M, N, C, mBase, nBase, 128, 128, 0, sbase);
    cp_commit();

    for (int i = 0; i < NIT; i++) {
        const int buf = i & 1;
        if (i + 1 < NIT) {
            LOAD_CHUNK(A, B, M, N, C, mBase, nBase, 128, 128, i + 1,
                       sbase + ((i + 1) & 1) * 32768u);
            cp_commit();
            cp_wait<1>();
        } else {
            cp_wait<0>();
        }
        __syncthreads();

        const uint32_t aTile = sbase + buf * 32768u;
        const uint32_t bTile = aTile + 16384u;
#pragma unroll
        for (int kk = 0; kk < 4; kk++) {
            uint32_t a[2][4], b[8][2];
#pragma unroll
            for (int mt = 0; mt < 2; mt++) {
                const int row = wm * 32 + mt * 16 + lrow_a;
                const uint32_t addr = aTile + row * 128 +
                    (((uint32_t)((kk * 2 + ahalf) ^ lxor)) << 4);
                ldsm_x4(a[mt][0], a[mt][1], a[mt][2], a[mt][3], addr);
            }
#pragma unroll
            for (int bt = 0; bt < 4; bt++) {
                const int row = wn * 64 + bt * 16 + lrow_b;
                const uint32_t addr = bTile + row * 128 +
                    (((uint32_t)((kk * 2 + bhalf) ^ lxor)) << 4);
                uint32_t r0, r1, r2, r3;
                ldsm_x4(r0, r1, r2, r3, addr);
                b[2 * bt][0] = r0;     b[2 * bt][1] = r1;
                b[2 * bt + 1][0] = r2; b[2 * bt + 1][1] = r3;
            }
#pragma unroll
            for (int mt = 0; mt < 2; mt++)
#pragma unroll
                for (int nt = 0; nt < 8; nt++)
                    mma16816(c[mt][nt], a[mt], b[nt]);
        }
        __syncthreads();
    }

    const int g  = lane >> 2;
    const int tg = lane & 3;
    const int Cout = N >> 6;
#pragma unroll
    for (int mt = 0; mt < 2; mt++) {
        const int m0 = mBase + wm * 32 + mt * 16 + g;
#pragma unroll
        for (int nt = 0; nt < 8; nt++) {
            const int n0 = nBase + wn * 64 + nt * 8 + tg * 2;
#pragma unroll
            for (int half = 0; half < 2; half++) {
                const int m = m0 + half * 8;
                const float v0 = c[mt][nt][half * 2 + 0];
                const float v1 = c[mt][nt][half * 2 + 1];
                if (MODE == 0) {
                    store_split(outSplit, M, Cout, m, n0,     fmaxf(v0 + aux[n0],     0.0f));
                    store_split(outSplit, M, Cout, m, n0 + 1, fmaxf(v1 + aux[n0 + 1], 0.0f));
                } else {
                    float2 r = make_float2(v0 + aux[n0], v1 + aux[n0 + 1]);
                    *(float2*)(outF + (size_t)m * N + n0) = r;
                }
            }
        }
    }
}

// ===================== fused recurrence step =================================
// gates = h(t) @ Whh'^T + xg'(t); cell math fused in epilogue.
// BM=128 (batch), BN=64 (16 j x 4 gates), grid (64, 2) = 128 CTAs.
#define GATE_W 68
__device__ __forceinline__ float sigf(float x) { return 1.0f / (1.0f + __expf(-x)); }

__global__ __launch_bounds__(256)
void rec_step_k(const __nv_bfloat16* __restrict__ hcR, __nv_bfloat16* __restrict__ hcW,
                const __nv_bfloat16* __restrict__ whh, const float* __restrict__ xg,
                const float* __restrict__ W_out,
                float* __restrict__ out, float* __restrict__ hT, float* __restrict__ cT,
                int t)
{
    extern __shared__ char smraw[];
    const uint32_t sbase = smem_u32(smraw);   // [2 bufs][A 16KB | B 8KB] = 48KB
    float* gate_sm = (float*)smraw;           // aliases stages post-mainloop

    const int tid  = threadIdx.x;
    const int lane = tid & 31;
    const int wid  = tid >> 5;
    const int wm   = wid & 3;       // 4 warps x 32 rows
    const int wn   = wid >> 2;      // 2 warps x 32 cols
    const int nBase = blockIdx.x * 64;
    const int mBase = blockIdx.y * 128;
    const int C = 16, NIT = 48;

    float c[2][4][4];
#pragma unroll
    for (int i = 0; i < 2; i++)
#pragma unroll
        for (int j = 0; j < 4; j++)
#pragma unroll
            for (int k = 0; k < 4; k++) c[i][j][k] = 0.0f;

    const int lrow_a = ((lane >> 3) & 1) * 8 + (lane & 7);
    const int lrow_b = (lane >> 4) * 8 + (lane & 7);
    const int lxor   = lane & 7;
    const int ahalf  = lane >> 4;
    const int bhalf  = (lane >> 3) & 1;

    LOAD_CHUNK(hcR, whh, 256, 4096, C, mBase, nBase, 128, 64, 0, sbase);
    cp_commit();

    for (int i = 0; i < NIT; i++) {
        const int buf = i & 1;
        if (i + 1 < NIT) {
            LOAD_CHUNK(hcR, whh, 256, 4096, C, mBase, nBase, 128, 64, i + 1,
                       sbase + ((i + 1) & 1) * 24576u);
            cp_commit();
            cp_wait<1>();
        } else {
            cp_wait<0>();
        }
        __syncthreads();

        const uint32_t aTile = sbase + buf * 24576u;
        const uint32_t bTile = aTile + 16384u;
#pragma unroll
        for (int kk = 0; kk < 4; kk++) {
            uint32_t a[2][4], b[4][2];
#pragma unroll
            for (int mt = 0; mt < 2; mt++) {
                const int row = wm * 32 + mt * 16 + lrow_a;
                const uint32_t addr = aTile + row * 128 +
                    (((uint32_t)((kk * 2 + ahalf) ^ lxor)) << 4);
                ldsm_x4(a[mt][0], a[mt][1], a[mt][2], a[mt][3], addr);
            }
#pragma unroll
            for (int bt = 0; bt < 2; bt++) {
                const int row = wn * 32 + bt * 16 + lrow_b;
                const uint32_t addr = bTile + row * 128 +
                    (((uint32_t)((kk * 2 + bhalf) ^ lxor)) << 4);
                uint32_t r0, r1, r2, r3;
                ldsm_x4(r0, r1, r2, r3, addr);
                b[2 * bt][0] = r0;     b[2 * bt][1] = r1;
                b[2 * bt + 1][0] = r2; b[2 * bt + 1][1] = r3;
            }
#pragma unroll
            for (int mt = 0; mt < 2; mt++)
#pragma unroll
                for (int nt = 0; nt < 4; nt++)
                    mma16816(c[mt][nt], a[mt], b[nt]);
        }
        __syncthreads();
    }

    // stage gates (+xg, bias already folded into xg) into smem
    const int g  = lane >> 2;
    const int tg = lane & 3;
#pragma unroll
    for (int mt = 0; mt < 2; mt++) {
#pragma unroll
        for (int nt = 0; nt < 4; nt++) {
            const int col = wn * 32 + nt * 8 + tg * 2;
#pragma unroll
            for (int half = 0; half < 2; half++) {
                const int row = wm * 32 + mt * 16 + g + half * 8;
                const float* xp = xg + (size_t)(mBase + row) * GG + nBase + col;
                gate_sm[row * GATE_W + col]     = c[mt][nt][half * 2 + 0] + xp[0];
                gate_sm[row * GATE_W + col + 1] = c[mt][nt][half * 2 + 1] + xp[1];
            }
        }
    }
    __syncthreads();

    // cell math: 128 b x 16 j pairs; thread -> b = tid>>1, 8 j's
    const int bloc = tid >> 1;
    const int b = mBase + bloc;
    const int jh = (tid & 1) * 8;
    float osum = 0.0f;
#pragma unroll
    for (int jj = 0; jj < 8; jj++) {
        const int jloc = jh + jj;
        const int j = (nBase >> 2) + jloc;
        const float4 gt = *(const float4*)&gate_sm[bloc * GATE_W + jloc * 4];
        const float ig = sigf(gt.x);
        const float fg = sigf(gt.y);
        const float gg = tanhf(gt.z);
        const float og = sigf(gt.w);
        const float cc = fg * g_c[b * HH + j] + ig * gg;
        const float h  = og * tanhf(cc);
        g_c[b * HH + j] = cc;

        const __nv_bfloat16 hi = __float2bfloat16(h);
        const __nv_bfloat16 lo = __float2bfloat16(h - __bfloat162float(hi));
        const int chunk = j >> 6, col = j & 63;
        hcW[((size_t)chunk * BB + b) * 64 + col] = hi;
        hcW[((size_t)(16 + chunk) * BB + b) * 64 + col] = lo;

        osum += h * W_out[j];
        if (t == TT - 1) { hT[b * HH + j] = h; cT[b * HH + j] = cc; }
    }
    atomicAdd(&out[t * BB + b], osum);
}

// ===================== conversion / pointwise kernels ========================
__global__ void split_k(const float* __restrict__ src, __nv_bfloat16* __restrict__ dst,
                        int R, int K)
{
    const size_t i = (size_t)blockIdx.x * blockDim.x + threadIdx.x;
    const int r = (int)(i / K);
    const int k = (int)(i - (size_t)r * K);
    const float x = src[i];
    const __nv_bfloat16 hi = __float2bfloat16(x);
    const __nv_bfloat16 lo = __float2bfloat16(x - __bfloat162float(hi));
    const int C = K >> 6;
    const int chunk = k >> 6, col = k & 63;
    dst[((size_t)chunk * R + r) * 64 + col] = hi;
    dst[((size_t)(C + chunk) * R + r) * 64 + col] = lo;
}

// gate-permuted split: dest row r' = j*4+g for src row r = g*1024+j  (R=4096,K=1024)
__global__ void split_perm_k(const float* __restrict__ src, __nv_bfloat16* __restrict__ dst)
{
    const size_t i = (size_t)blockIdx.x * blockDim.x + threadIdx.x;
    const int r = (int)(i >> 10);            // src row
    const int k = (int)(i & 1023);
    const int gt = r >> 10, j = r & 1023;
    const int rp = j * 4 + gt;
    const float x = src[i];
    const __nv_bfloat16 hi = __float2bfloat16(x);
    const __nv_bfloat16 lo = __float2bfloat16(x - __bfloat162float(hi));
    const int chunk = k >> 6, col = k & 63;
    dst[((size_t)chunk * 4096 + rp) * 64 + col] = hi;
    dst[((size_t)(16 + chunk) * 4096 + rp) * 64 + col] = lo;
}

__global__ void combine_bias_k(const float* __restrict__ b_ih, const float* __restrict__ b_hh)
{
    int i = blockIdx.x * blockDim.x + threadIdx.x;  // dest index n' = j*4+g
    if (i < GG) {
        const int gt = i & 3, j = i >> 2;
        const int s = gt * HH + j;
        g_bias[i] = b_ih[s] + b_hh[s];
    }
}

__global__ void init_state_k(const float* __restrict__ h0, const float* __restrict__ c0)
{
    const int i = blockIdx.x * blockDim.x + threadIdx.x;   // [0, B*H)
    const int b = i >> 10, j = i & 1023;
    g_c[i] = c0[i];
    const float h = h0[i];
    const __nv_bfloat16 hi = __float2bfloat16(h);
    const __nv_bfloat16 lo = __float2bfloat16(h - __bfloat162float(hi));
    const int chunk = j >> 6, col = j & 63;
    g_hc[((size_t)chunk * BB + b) * 64 + col] = hi;
    g_hc[((size_t)(16 + chunk) * BB + b) * 64 + col] = lo;
}

__global__ void out_init_k(float* __restrict__ out, const float* __restrict__ b_out)
{
    const int i = blockIdx.x * blockDim.x + threadIdx.x;
    if (i < TT * BB) out[i] = b_out[0];
}

// ===================== launch ================================================
#define SMEM_BIG 65536
#define SMEM_REC 49152

extern "C" void kernel_launch(void* const* d_in, const int* in_sizes, int n_in,
                              void* d_out, int out_size)
{
    const float* inputs = (const float*)d_in[0];
    const float* h0     = (const float*)d_in[1];
    const float* c0     = (const float*)d_in[2];
    const float* W1     = (const float*)d_in[3];
    const float* b1     = (const float*)d_in[4];
    const float* W_ih   = (const float*)d_in[5];
    const float* W_hh   = (const float*)d_in[6];
    const float* b_ih   = (const float*)d_in[7];
    const float* b_hh   = (const float*)d_in[8];
    const float* W_out  = (const float*)d_in[9];
    const float* b_out  = (const float*)d_in[10];

    float* out = (float*)d_out;
    float* hT  = out + TT * BB;
    float* cT  = hT + BB * HH;

    __nv_bfloat16 *pinc, *pxc, *pw1c, *pwihc, *pwhhc, *phc;
    float *pxg, *pbias;
    cudaGetSymbolAddress((void**)&pinc,  g_inc);
    cudaGetSymbolAddress((void**)&pxc,   g_xc);
    cudaGetSymbolAddress((void**)&pw1c,  g_w1c);
    cudaGetSymbolAddress((void**)&pwihc, g_wihc);
    cudaGetSymbolAddress((void**)&pwhhc, g_whhc);
    cudaGetSymbolAddress((void**)&phc,   g_hc);
    cudaGetSymbolAddress((void**)&pxg,   g_xg);
    cudaGetSymbolAddress((void**)&pbias, g_bias);

    cudaFuncSetAttribute(gemm_mma<0>, cudaFuncAttributeMaxDynamicSharedMemorySize, SMEM_BIG);
    cudaFuncSetAttribute(gemm_mma<1>, cudaFuncAttributeMaxDynamicSharedMemorySize, SMEM_BIG);
    cudaFuncSetAttribute(rec_step_k,  cudaFuncAttributeMaxDynamicSharedMemorySize, SMEM_REC);

    // conversions
    split_k<<<(32768 * 512) / 256, 256>>>(inputs, pinc, 32768, 512);
    split_k<<<(1024 * 512) / 256, 256>>>(W1, pw1c, 1024, 512);
    split_perm_k<<<(4096 * 1024) / 256, 256>>>(W_ih, pwihc);
    split_perm_k<<<(4096 * 1024) / 256, 256>>>(W_hh, pwhhc);
    combine_bias_k<<<GG / 256, 256>>>(b_ih, b_hh);
    init_state_k<<<(BB * HH) / 256, 256>>>(h0, c0);
    out_init_k<<<(TT * BB) / 256, 256>>>(out, b_out);

    // GEMM1: x = relu(inputs @ W1^T + b1) -> split store g_xc
    {
        dim3 grid(HH / 128, 32768 / 128);
        gemm_mma<0><<<grid, 256, SMEM_BIG>>>(pinc, pw1c, b1, nullptr, pxc, 32768, HH, 8);
    }
    // GEMM2: xg' = x @ W_ih'^T + bias' -> g_xg (gate-permuted cols)
    {
        dim3 grid(GG / 128, 32768 / 128);
        gemm_mma<1><<<grid, 256, SMEM_BIG>>>(pxc, pwihc, pbias, pxg, nullptr, 32768, GG, 16);
    }
    // fused recurrence: 1 kernel per step
    {
        dim3 grid(GG / 64, BB / 128);   // 64 x 2 = 128 CTAs
        for (int t = 0; t < TT; t++) {
            rec_step_k<<<grid, 256, SMEM_REC>>>(
                phc + (t & 1) * HSPLIT, phc + ((t + 1) & 1) * HSPLIT,
                pwhhc, pxg + (size_t)t * BB * GG, W_out, out, hT, cT, t);
        }
    }
}

// round 5
// speedup vs baseline: 3.5191x; 1.1383x over previous
#include <cuda_runtime.h>
#include <cuda_fp16.h>
#include <math.h>
#include <stdint.h>

#define TT 128
#define BB 256
#define DD 512
#define HH 1024
#define GG 4096   // 4*H

// ===================== scratch (static device globals) ======================
// chunk-major fp16 operand buffers: [chunks][R rows][64 halves], 128B rows
__device__ __align__(16) __half g_inc [(size_t)16 * 32768 * 64]; // inputs hi+lo (C=8)
__device__ __align__(16) __half g_xc  [(size_t)32 * 32768 * 64]; // x hi+lo      (C=16)
__device__ __align__(16) __half g_w1c [(size_t)8  * 1024  * 64]; // W1 hi only
__device__ __align__(16) __half g_wihc[(size_t)16 * 4096  * 64]; // W_ih hi only (gate-perm)
__device__ __align__(16) __half g_whhc[(size_t)32 * 4096  * 64]; // W_hh hi+lo   (gate-perm)
#define HSPLIT ((size_t)32 * 256 * 64)
__device__ __align__(16) __half g_hc  [2 * HSPLIT];              // h hi+lo, ping-pong
__device__ __align__(16) float g_xg[(size_t)TT * BB * GG];       // gate-perm cols
__device__ __align__(16) float g_c[BB * HH];
__device__ __align__(16) float g_bias[GG];                       // gate-perm

// ===================== PTX helpers ==========================================
__device__ __forceinline__ uint32_t smem_u32(const void* p) {
    return (uint32_t)__cvta_generic_to_shared(p);
}
__device__ __forceinline__ void cp_async16(uint32_t dst, const void* src) {
    asm volatile("cp.async.cg.shared.global [%0], [%1], 16;" :: "r"(dst), "l"(src));
}
__device__ __forceinline__ void cp_commit() {
    asm volatile("cp.async.commit_group;" ::: "memory");
}
template<int N>
__device__ __forceinline__ void cp_wait() {
    asm volatile("cp.async.wait_group %0;" :: "n"(N) : "memory");
}
__device__ __forceinline__ void ldsm_x4(uint32_t& r0, uint32_t& r1, uint32_t& r2, uint32_t& r3,
                                        uint32_t addr) {
    asm volatile("ldmatrix.sync.aligned.m8n8.x4.shared.b16 {%0,%1,%2,%3}, [%4];"
                 : "=r"(r0), "=r"(r1), "=r"(r2), "=r"(r3) : "r"(addr));
}
__device__ __forceinline__ void mma16816(float* c, const uint32_t* a, const uint32_t* b) {
    asm volatile(
        "mma.sync.aligned.m16n8k16.row.col.f32.f16.f16.f32 "
        "{%0,%1,%2,%3}, {%4,%5,%6,%7}, {%8,%9}, {%0,%1,%2,%3};"
        : "+f"(c[0]), "+f"(c[1]), "+f"(c[2]), "+f"(c[3])
        : "r"(a[0]), "r"(a[1]), "r"(a[2]), "r"(a[3]), "r"(b[0]), "r"(b[1]));
}

__device__ __forceinline__ void split2(float v, __half& hi, __half& lo) {
    hi = __float2half_rn(v);
    lo = __float2half_rn(v - __half2float(hi));
}

__device__ __forceinline__ void store_split(__half* dst, int M, int Cout,
                                            int m, int n, float v) {
    __half hi, lo; split2(v, hi, lo);
    const int chunk = n >> 6, col = n & 63;
    dst[((size_t)chunk * M + m) * 64 + col] = hi;
    dst[((size_t)(Cout + chunk) * M + m) * 64 + col] = lo;
}

// chunk loader: A tile RA rows, B tile RB rows, 128B rows, XOR-swizzled
#define LOAD_CHUNK(A_, B_, M_, N_, mB_, nB_, RA_, RB_, ac_, bc_, dA_)             \
    do {                                                                          \
        const char* As_ = (const char*)((A_) + ((size_t)(ac_) * (M_) + (mB_)) * 64);\
        const char* Bs_ = (const char*)((B_) + ((size_t)(bc_) * (N_) + (nB_)) * 64);\
        const uint32_t dB_ = (dA_) + (RA_) * 128u;                                \
        _Pragma("unroll")                                                         \
        for (int q_ = 0; q_ < (RA_) / 32; q_++) {                                 \
            const int e_ = tid + q_ * 256;                                        \
            const int r_ = e_ >> 3, s_ = e_ & 7;                                  \
            const uint32_t off_ = r_ * 128 + (((uint32_t)(s_ ^ (r_ & 7))) << 4);  \
            cp_async16((dA_) + off_, As_ + r_ * 128 + s_ * 16);                   \
        }                                                                         \
        _Pragma("unroll")                                                         \
        for (int q_ = 0; q_ < (RB_) / 32; q_++) {                                 \
            const int e_ = tid + q_ * 256;                                        \
            const int r_ = e_ >> 3, s_ = e_ & 7;                                  \
            const uint32_t off_ = r_ * 128 + (((uint32_t)(s_ ^ (r_ & 7))) << 4);  \
            cp_async16(dB_ + off_, Bs_ + r_ * 128 + s_ * 16);                     \
        }                                                                         \
    } while (0)

// pass mapping: 2-pass -> (A hi,B hi),(A lo,B hi);  B has only C chunks
__device__ __forceinline__ void chunk_map2(int i, int C, int& ac, int& bc) {
    const int p = i / C, ci = i - p * C;
    ac = (p == 1) ? C + ci : ci;
    bc = ci;
}

// ===================== big GEMMs (BM=BN=128, 2-pass fp16, 2 CTA/SM) ==========
// MODE 0: v=relu(v+aux[n]) -> split store; MODE 1: v=v+aux[n] -> outF
template<int MODE>
__global__ __launch_bounds__(256, 2)
void gemm_mma(const __half* __restrict__ A, const __half* __restrict__ B,
              const float* __restrict__ aux, float* __restrict__ outF,
              __half* __restrict__ outSplit, int M, int N, int C)
{
    extern __shared__ char smraw[];
    const uint32_t sbase = smem_u32(smraw);   // [2 bufs][A 16KB | B 16KB]

    const int tid  = threadIdx.x;
    const int lane = tid & 31;
    const int wid  = tid >> 5;
    const int wm   = wid & 3;
    const int wn   = wid >> 2;
    const int mBase = blockIdx.y * 128;
    const int nBase = blockIdx.x * 128;
    const int NIT = 2 * C;

    float c[2][8][4];
#pragma unroll
    for (int i = 0; i < 2; i++)
#pragma unroll
        for (int j = 0; j < 8; j++)
#pragma unroll
            for (int k = 0; k < 4; k++) c[i][j][k] = 0.0f;

    const int lrow_a = ((lane >> 3) & 1) * 8 + (lane & 7);
    const int lrow_b = (lane >> 4) * 8 + (lane & 7);
    const int lxor   = lane & 7;
    const int ahalf  = lane >> 4;
    const int bhalf  = (lane >> 3) & 1;

    {
        int ac, bc; chunk_map2(0, C, ac, bc);
        LOAD_CHUNK(A, B, M, N, mBase, nBase, 128, 128, ac, bc, sbase);
        cp_commit();
    }

    for (int i = 0; i < NIT; i++) {
        const int buf = i & 1;
        if (i + 1 < NIT) {
            int ac, bc; chunk_map2(i + 1, C, ac, bc);
            LOAD_CHUNK(A, B, M, N, mBase, nBase, 128, 128, ac, bc,
                       sbase + ((i + 1) & 1) * 32768u);
            cp_commit();
            cp_wait<1>();
        } else {
            cp_wait<0>();
        }
        __syncthreads();

        const uint32_t aTile = sbase + buf * 32768u;
        const uint32_t bTile = aTile + 16384u;
#pragma unroll
        for (int kk = 0; kk < 4; kk++) {
            uint32_t a[2][4], b[8][2];
#pragma unroll
            for (int mt = 0; mt < 2; mt++) {
                const int row = wm * 32 + mt * 16 + lrow_a;
                const uint32_t addr = aTile + row * 128 +
                    (((uint32_t)((kk * 2 + ahalf) ^ lxor)) << 4);
                ldsm_x4(a[mt][0], a[mt][1], a[mt][2], a[mt][3], addr);
            }
#pragma unroll
            for (int bt = 0; bt < 4; bt++) {
                const int row = wn * 64 + bt * 16 + lrow_b;
                const uint32_t addr = bTile + row * 128 +
                    (((uint32_t)((kk * 2 + bhalf) ^ lxor)) << 4);
                uint32_t r0, r1, r2, r3;
                ldsm_x4(r0, r1, r2, r3, addr);
                b[2 * bt][0] = r0;     b[2 * bt][1] = r1;
                b[2 * bt + 1][0] = r2; b[2 * bt + 1][1] = r3;
            }
#pragma unroll
            for (int mt = 0; mt < 2; mt++)
#pragma unroll
                for (int nt = 0; nt < 8; nt++)
                    mma16816(c[mt][nt], a[mt], b[nt]);
        }
        __syncthreads();
    }

    const int g  = lane >> 2;
    const int tg = lane & 3;
    const int Cout = N >> 6;
#pragma unroll
    for (int mt = 0; mt < 2; mt++) {
        const int m0 = mBase + wm * 32 + mt * 16 + g;
#pragma unroll
        for (int nt = 0; nt < 8; nt++) {
            const int n0 = nBase + wn * 64 + nt * 8 + tg * 2;
#pragma unroll
            for (int half = 0; half < 2; half++) {
                const int m = m0 + half * 8;
                const float v0 = c[mt][nt][half * 2 + 0];
                const float v1 = c[mt][nt][half * 2 + 1];
                if (MODE == 0) {
                    store_split(outSplit, M, Cout, m, n0,     fmaxf(v0 + aux[n0],     0.0f));
                    store_split(outSplit, M, Cout, m, n0 + 1, fmaxf(v1 + aux[n0 + 1], 0.0f));
                } else {
                    float2 r = make_float2(v0 + aux[n0], v1 + aux[n0 + 1]);
                    *(float2*)(outF + (size_t)m * N + n0) = r;
                }
            }
        }
    }
}

// ===================== fused recurrence step (3-pass fp16) ===================
#define GATE_W 68
__device__ __forceinline__ float sigf(float x) { return 1.0f / (1.0f + __expf(-x)); }

__global__ __launch_bounds__(256)
void rec_step_k(const __half* __restrict__ hcR, __half* __restrict__ hcW,
                const __half* __restrict__ whh, const float* __restrict__ xg,
                const float* __restrict__ W_out,
                float* __restrict__ out, float* __restrict__ hT, float* __restrict__ cT,
                int t)
{
    extern __shared__ char smraw[];
    const uint32_t sbase = smem_u32(smraw);   // [2 bufs][A 16KB | B 8KB] = 48KB
    float* gate_sm = (float*)smraw;

    const int tid  = threadIdx.x;
    const int lane = tid & 31;
    const int wid  = tid >> 5;
    const int wm   = wid & 3;
    const int wn   = wid >> 2;
    const int nBase = blockIdx.x * 64;
    const int mBase = blockIdx.y * 128;
    const int C = 16, NIT = 48;

    float c[2][4][4];
#pragma unroll
    for (int i = 0; i < 2; i++)
#pragma unroll
        for (int j = 0; j < 4; j++)
#pragma unroll
            for (int k = 0; k < 4; k++) c[i][j][k] = 0.0f;

    const int lrow_a = ((lane >> 3) & 1) * 8 + (lane & 7);
    const int lrow_b = (lane >> 4) * 8 + (lane & 7);
    const int lxor   = lane & 7;
    const int ahalf  = lane >> 4;
    const int bhalf  = (lane >> 3) & 1;

    // 3-pass map: p0 (Ahi,Bhi)  p1 (Ahi,Blo)  p2 (Alo,Bhi)
#define MAP3(i_, ac_, bc_)                              \
    {   const int p_ = (i_) / C, ci_ = (i_) - p_ * C;   \
        ac_ = (p_ == 2) ? C + ci_ : ci_;                \
        bc_ = (p_ == 1) ? C + ci_ : ci_; }

    {
        int ac, bc; MAP3(0, ac, bc);
        LOAD_CHUNK(hcR, whh, 256, 4096, mBase, nBase, 128, 64, ac, bc, sbase);
        cp_commit();
    }

    for (int i = 0; i < NIT; i++) {
        const int buf = i & 1;
        if (i + 1 < NIT) {
            int ac, bc; MAP3(i + 1, ac, bc);
            LOAD_CHUNK(hcR, whh, 256, 4096, mBase, nBase, 128, 64, ac, bc,
                       sbase + ((i + 1) & 1) * 24576u);
            cp_commit();
            cp_wait<1>();
        } else {
            cp_wait<0>();
        }
        __syncthreads();

        const uint32_t aTile = sbase + buf * 24576u;
        const uint32_t bTile = aTile + 16384u;
#pragma unroll
        for (int kk = 0; kk < 4; kk++) {
            uint32_t a[2][4], b[4][2];
#pragma unroll
            for (int mt = 0; mt < 2; mt++) {
                const int row = wm * 32 + mt * 16 + lrow_a;
                const uint32_t addr = aTile + row * 128 +
                    (((uint32_t)((kk * 2 + ahalf) ^ lxor)) << 4);
                ldsm_x4(a[mt][0], a[mt][1], a[mt][2], a[mt][3], addr);
            }
#pragma unroll
            for (int bt = 0; bt < 2; bt++) {
                const int row = wn * 32 + bt * 16 + lrow_b;
                const uint32_t addr = bTile + row * 128 +
                    (((uint32_t)((kk * 2 + bhalf) ^ lxor)) << 4);
                uint32_t r0, r1, r2, r3;
                ldsm_x4(r0, r1, r2, r3, addr);
                b[2 * bt][0] = r0;     b[2 * bt][1] = r1;
                b[2 * bt + 1][0] = r2; b[2 * bt + 1][1] = r3;
            }
#pragma unroll
            for (int mt = 0; mt < 2; mt++)
#pragma unroll
                for (int nt = 0; nt < 4; nt++)
                    mma16816(c[mt][nt], a[mt], b[nt]);
        }
        __syncthreads();
    }
#undef MAP3

    const int g  = lane >> 2;
    const int tg = lane & 3;
#pragma unroll
    for (int mt = 0; mt < 2; mt++) {
#pragma unroll
        for (int nt = 0; nt < 4; nt++) {
            const int col = wn * 32 + nt * 8 + tg * 2;
#pragma unroll
            for (int half = 0; half < 2; half++) {
                const int row = wm * 32 + mt * 16 + g + half * 8;
                const float* xp = xg + (size_t)(mBase + row) * GG + nBase + col;
                gate_sm[row * GATE_W + col]     = c[mt][nt][half * 2 + 0] + xp[0];
                gate_sm[row * GATE_W + col + 1] = c[mt][nt][half * 2 + 1] + xp[1];
            }
        }
    }
    __syncthreads();

    const int bloc = tid >> 1;
    const int b = mBase + bloc;
    const int jh = (tid & 1) * 8;
    float osum = 0.0f;
#pragma unroll
    for (int jj = 0; jj < 8; jj++) {
        const int jloc = jh + jj;
        const int j = (nBase >> 2) + jloc;
        const float4 gt = *(const float4*)&gate_sm[bloc * GATE_W + jloc * 4];
        const float ig = sigf(gt.x);
        const float fg = sigf(gt.y);
        const float gg = tanhf(gt.z);
        const float og = sigf(gt.w);
        const float cc = fg * g_c[b * HH + j] + ig * gg;
        const float h  = og * tanhf(cc);
        g_c[b * HH + j] = cc;

        __half hi, lo; split2(h, hi, lo);
        const int chunk = j >> 6, col = j & 63;
        hcW[((size_t)chunk * BB + b) * 64 + col] = hi;
        hcW[((size_t)(16 + chunk) * BB + b) * 64 + col] = lo;

        osum += h * W_out[j];
        if (t == TT - 1) { hT[b * HH + j] = h; cT[b * HH + j] = cc; }
    }
    atomicAdd(&out[t * BB + b], osum);
}

// ===================== conversion / pointwise kernels ========================
// full hi+lo split (inputs)
__global__ void split_k(const float* __restrict__ src, __half* __restrict__ dst,
                        int R, int K)
{
    const size_t i = (size_t)blockIdx.x * blockDim.x + threadIdx.x;
    const int r = (int)(i / K);
    const int k = (int)(i - (size_t)r * K);
    __half hi, lo; split2(src[i], hi, lo);
    const int C = K >> 6;
    const int chunk = k >> 6, col = k & 63;
    dst[((size_t)chunk * R + r) * 64 + col] = hi;
    dst[((size_t)(C + chunk) * R + r) * 64 + col] = lo;
}

// hi-only (W1)
__global__ void split_hi_k(const float* __restrict__ src, __half* __restrict__ dst,
                           int R, int K)
{
    const size_t i = (size_t)blockIdx.x * blockDim.x + threadIdx.x;
    const int r = (int)(i / K);
    const int k = (int)(i - (size_t)r * K);
    const int chunk = k >> 6, col = k & 63;
    dst[((size_t)chunk * R + r) * 64 + col] = __float2half_rn(src[i]);
}

// gate-permuted, hi-only (W_ih): dest row r' = j*4+g
__global__ void split_perm_hi_k(const float* __restrict__ src, __half* __restrict__ dst)
{
    const size_t i = (size_t)blockIdx.x * blockDim.x + threadIdx.x;
    const int r = (int)(i >> 10);
    const int k = (int)(i & 1023);
    const int gt = r >> 10, j = r & 1023;
    const int rp = j * 4 + gt;
    const int chunk = k >> 6, col = k & 63;
    dst[((size_t)chunk * 4096 + rp) * 64 + col] = __float2half_rn(src[i]);
}

// gate-permuted, hi+lo (W_hh)
__global__ void split_perm_k(const float* __restrict__ src, __half* __restrict__ dst)
{
    const size_t i = (size_t)blockIdx.x * blockDim.x + threadIdx.x;
    const int r = (int)(i >> 10);
    const int k = (int)(i & 1023);
    const int gt = r >> 10, j = r & 1023;
    const int rp = j * 4 + gt;
    __half hi, lo; split2(src[i], hi, lo);
    const int chunk = k >> 6, col = k & 63;
    dst[((size_t)chunk * 4096 + rp) * 64 + col] = hi;
    dst[((size_t)(16 + chunk) * 4096 + rp) * 64 + col] = lo;
}

__global__ void combine_bias_k(const float* __restrict__ b_ih, const float* __restrict__ b_hh)
{
    int i = blockIdx.x * blockDim.x + threadIdx.x;
    if (i < GG) {
        const int gt = i & 3, j = i >> 2;
        const int s = gt * HH + j;
        g_bias[i] = b_ih[s] + b_hh[s];
    }
}

__global__ void init_state_k(const float* __restrict__ h0, const float* __restrict__ c0)
{
    const int i = blockIdx.x * blockDim.x + threadIdx.x;
    const int b = i >> 10, j = i & 1023;
    g_c[i] = c0[i];
    __half hi, lo; split2(h0[i], hi, lo);
    const int chunk = j >> 6, col = j & 63;
    g_hc[((size_t)chunk * BB + b) * 64 + col] = hi;
    g_hc[((size_t)(16 + chunk) * BB + b) * 64 + col] = lo;
}

__global__ void out_init_k(float* __restrict__ out, const float* __restrict__ b_out)
{
    const int i = blockIdx.x * blockDim.x + threadIdx.x;
    if (i < TT * BB) out[i] = b_out[0];
}

// ===================== launch ================================================
#define SMEM_BIG 65536
#define SMEM_REC 49152

extern "C" void kernel_launch(void* const* d_in, const int* in_sizes, int n_in,
                              void* d_out, int out_size)
{
    const float* inputs = (const float*)d_in[0];
    const float* h0     = (const float*)d_in[1];
    const float* c0     = (const float*)d_in[2];
    const float* W1     = (const float*)d_in[3];
    const float* b1     = (const float*)d_in[4];
    const float* W_ih   = (const float*)d_in[5];
    const float* W_hh   = (const float*)d_in[6];
    const float* b_ih   = (const float*)d_in[7];
    const float* b_hh   = (const float*)d_in[8];
    const float* W_out  = (const float*)d_in[9];
    const float* b_out  = (const float*)d_in[10];

    float* out = (float*)d_out;
    float* hT  = out + TT * BB;
    float* cT  = hT + BB * HH;

    __half *pinc, *pxc, *pw1c, *pwihc, *pwhhc, *phc;
    float *pxg, *pbias;
    cudaGetSymbolAddress((void**)&pinc,  g_inc);
    cudaGetSymbolAddress((void**)&pxc,   g_xc);
    cudaGetSymbolAddress((void**)&pw1c,  g_w1c);
    cudaGetSymbolAddress((void**)&pwihc, g_wihc);
    cudaGetSymbolAddress((void**)&pwhhc, g_whhc);
    cudaGetSymbolAddress((void**)&phc,   g_hc);
    cudaGetSymbolAddress((void**)&pxg,   g_xg);
    cudaGetSymbolAddress((void**)&pbias, g_bias);

    cudaFuncSetAttribute(gemm_mma<0>, cudaFuncAttributeMaxDynamicSharedMemorySize, SMEM_BIG);
    cudaFuncSetAttribute(gemm_mma<1>, cudaFuncAttributeMaxDynamicSharedMemorySize, SMEM_BIG);
    cudaFuncSetAttribute(rec_step_k,  cudaFuncAttributeMaxDynamicSharedMemorySize, SMEM_REC);

    // conversions
    split_k<<<(32768 * 512) / 256, 256>>>(inputs, pinc, 32768, 512);
    split_hi_k<<<(1024 * 512) / 256, 256>>>(W1, pw1c, 1024, 512);
    split_perm_hi_k<<<(4096 * 1024) / 256, 256>>>(W_ih, pwihc);
    split_perm_k<<<(4096 * 1024) / 256, 256>>>(W_hh, pwhhc);
    combine_bias_k<<<GG / 256, 256>>>(b_ih, b_hh);
    init_state_k<<<(BB * HH) / 256, 256>>>(h0, c0);
    out_init_k<<<(TT * BB) / 256, 256>>>(out, b_out);

    // GEMM1: x = relu(inputs @ W1^T + b1) -> split store g_xc  (2-pass, C=8)
    {
        dim3 grid(HH / 128, 32768 / 128);
        gemm_mma<0><<<grid, 256, SMEM_BIG>>>(pinc, pw1c, b1, nullptr, pxc, 32768, HH, 8);
    }
    // GEMM2: xg' = x @ W_ih'^T + bias' -> g_xg  (2-pass, C=16)
    {
        dim3 grid(GG / 128, 32768 / 128);
        gemm_mma<1><<<grid, 256, SMEM_BIG>>>(pxc, pwihc, pbias, pxg, nullptr, 32768, GG, 16);
    }
    // fused recurrence: 1 kernel per step (3-pass fp16)
    {
        dim3 grid(GG / 64, BB / 128);
        for (int t = 0; t < TT; t++) {
            rec_step_k<<<grid, 256, SMEM_REC>>>(
                phc + (t & 1) * HSPLIT, phc + ((t + 1) & 1) * HSPLIT,
                pwhhc, pxg + (size_t)t * BB * GG, W_out, out, hT, cT, t);
        }
    }
}